// round 1
// baseline (speedup 1.0000x reference)
#include <cuda_runtime.h>
#include <cstddef>

// Shapes (fixed by the problem):
//   x:  (3*1024, 512)   Wq: (512, 512)   Wo: (512, 512)   bo: (512)
//   q = x @ Wq^T  -> (3072, 512), viewed as 3 planes of 32x32 positions, 8 heads x 64 dims
//   attention: per (plane, pos, head): 128 gathered keys (rows of q), softmax, weighted sum
//   out = ao @ Wo^T + bo -> (3072, 512)

#define LQ   1024
#define DDIM 512
#define ROWS 3072

__device__ float g_q [ROWS * DDIM];
__device__ float g_ao[ROWS * DDIM];

// ---------------------------------------------------------------------------
// GEMM: C[M,N] = A[M,K] @ B[N,K]^T (+ optional bias[N]); both K-contiguous.
// BM=128, BN=64, BK=16, 256 threads, 8x4 microtile.
// ---------------------------------------------------------------------------
#define BM 128
#define BN 64
#define BK 16

__global__ __launch_bounds__(256) void gemm_nt(
    const float* __restrict__ A, const float* __restrict__ B,
    const float* __restrict__ bias, float* __restrict__ C,
    int M, int N, int K)
{
    __shared__ float As[BK][BM + 4];   // row pitch 132 floats (16B aligned)
    __shared__ float Bs[BK][BN + 8];   // row pitch 72 floats  (16B aligned)

    const int bm  = blockIdx.y * BM;
    const int bn  = blockIdx.x * BN;
    const int tid = threadIdx.x;
    const int tx  = tid & 15;   // 16 cols of 4
    const int ty  = tid >> 4;   // 16 rows of 8

    const int arow = tid >> 1;        // 0..127
    const int ak   = (tid & 1) * 8;   // 0 or 8
    const int brow = tid >> 2;        // 0..63
    const int bk   = (tid & 3) * 4;   // 0,4,8,12

    const float* Aptr = A + (size_t)(bm + arow) * K + ak;
    const float* Bptr = B + (size_t)(bn + brow) * K + bk;

    float acc[8][4];
    #pragma unroll
    for (int u = 0; u < 8; u++)
        #pragma unroll
        for (int v = 0; v < 4; v++) acc[u][v] = 0.f;

    for (int k0 = 0; k0 < K; k0 += BK) {
        float4 a0 = *(const float4*)(Aptr + k0);
        float4 a1 = *(const float4*)(Aptr + k0 + 4);
        float4 b0 = *(const float4*)(Bptr + k0);
        As[ak + 0][arow] = a0.x; As[ak + 1][arow] = a0.y;
        As[ak + 2][arow] = a0.z; As[ak + 3][arow] = a0.w;
        As[ak + 4][arow] = a1.x; As[ak + 5][arow] = a1.y;
        As[ak + 6][arow] = a1.z; As[ak + 7][arow] = a1.w;
        Bs[bk + 0][brow] = b0.x; Bs[bk + 1][brow] = b0.y;
        Bs[bk + 2][brow] = b0.z; Bs[bk + 3][brow] = b0.w;
        __syncthreads();

        #pragma unroll
        for (int kk = 0; kk < BK; kk++) {
            float4 ar0 = *(const float4*)&As[kk][ty * 8];
            float4 ar1 = *(const float4*)&As[kk][ty * 8 + 4];
            float4 br  = *(const float4*)&Bs[kk][tx * 4];
            float a[8] = {ar0.x, ar0.y, ar0.z, ar0.w, ar1.x, ar1.y, ar1.z, ar1.w};
            float b[4] = {br.x, br.y, br.z, br.w};
            #pragma unroll
            for (int u = 0; u < 8; u++)
                #pragma unroll
                for (int v = 0; v < 4; v++)
                    acc[u][v] = fmaf(a[u], b[v], acc[u][v]);
        }
        __syncthreads();
    }

    float bv0 = 0.f, bv1 = 0.f, bv2 = 0.f, bv3 = 0.f;
    if (bias) {
        const float4 bb = *(const float4*)(bias + bn + tx * 4);
        bv0 = bb.x; bv1 = bb.y; bv2 = bb.z; bv3 = bb.w;
    }
    #pragma unroll
    for (int u = 0; u < 8; u++) {
        float4 o;
        o.x = acc[u][0] + bv0; o.y = acc[u][1] + bv1;
        o.z = acc[u][2] + bv2; o.w = acc[u][3] + bv3;
        *(float4*)(C + (size_t)(bm + ty * 8 + u) * N + bn + tx * 4) = o;
    }
}

// ---------------------------------------------------------------------------
// Key index mapping: for query plane p, key index f in [0,128), query col i,
// row j (both in [0,32)), return global row of g_q (srcplane*1024 + pos).
//
// Derived from the reference's p*_* concatenations (mid = 15):
//  p=0: [f2 col-keys(i) | f2 row15 | f3 col15 | f3 row j          ]
//  p=1: [f1 col-keys(i) | f1 row15 | f3 col(31-j) | f3 row15      ]
//  p=2: [f1 col15       | f1 row j | f3 col15 | f3 row(31-i)      ]
// ---------------------------------------------------------------------------
__device__ __forceinline__ int key_gpos(int p, int f, int i, int j)
{
    const int g = f >> 5;     // 0..3 (which 32-key group)
    const int r = f & 31;
    int pos, sp;
    if (p == 0) {
        sp = (f < 64) ? 1 : 2;
        pos = (g == 0) ? r * 32 + i
            : (g == 1) ? 480 + r          // 15*32 + r
            : (g == 2) ? r * 32 + 15
            :            j * 32 + r;
    } else if (p == 1) {
        sp = (f < 64) ? 0 : 2;
        pos = (g == 0) ? r * 32 + i
            : (g == 1) ? 480 + r
            : (g == 2) ? r * 32 + (31 - j)
            :            480 + r;
    } else {
        sp = (f < 64) ? 0 : 2;
        pos = (g == 0) ? r * 32 + 15
            : (g == 1) ? j * 32 + r
            : (g == 2) ? r * 32 + 15
            :            (31 - i) * 32 + r;
    }
    return sp * 1024 + pos;
}

// ---------------------------------------------------------------------------
// Attention: one CTA per (plane, query position); 8 warps = 8 heads.
// Phase A: lane = key-group offset, 4 scores/lane (uncoalesced but each lane
//          reads 256B contiguous -> full-line utilization).
// Phase B: lane = dim pair, loop over 128 keys (perfectly coalesced).
// Keys are gathered straight from g_q (all resident in L2).
// ---------------------------------------------------------------------------
__global__ __launch_bounds__(256) void attn_kernel()
{
    const int bq   = blockIdx.x;      // 0..3071
    const int p    = bq >> 10;
    const int idx  = bq & 1023;
    const int i    = idx & 31;        // column
    const int j    = idx >> 5;        // row
    const int h    = threadIdx.x >> 5;
    const int lane = threadIdx.x & 31;

    __shared__ float sq [8][64];
    __shared__ float spb[8][128];
    __shared__ int   spos[128];

    // load q vector for this (query, head): coalesced float2 per lane
    const float* qrow = g_q + (size_t)bq * DDIM + h * 64;
    float2 qv = *(const float2*)(qrow + 2 * lane);
    sq[h][2 * lane]     = qv.x;
    sq[h][2 * lane + 1] = qv.y;

    // key index table (shared across heads: independent of h)
    if (threadIdx.x < 128) spos[threadIdx.x] = key_gpos(p, threadIdx.x, i, j);
    __syncthreads();

    // ---- Phase A: scores (4 keys per lane) ----
    float s[4];
    #pragma unroll
    for (int t = 0; t < 4; t++) {
        const int f = lane + t * 32;
        const float4* kv = (const float4*)(g_q + (size_t)spos[f] * DDIM + h * 64);
        float acc = 0.f;
        #pragma unroll
        for (int d4 = 0; d4 < 16; d4++) {
            float4 k4 = kv[d4];
            acc = fmaf(sq[h][d4 * 4 + 0], k4.x, acc);
            acc = fmaf(sq[h][d4 * 4 + 1], k4.y, acc);
            acc = fmaf(sq[h][d4 * 4 + 2], k4.z, acc);
            acc = fmaf(sq[h][d4 * 4 + 3], k4.w, acc);
        }
        s[t] = acc * 0.125f;   // 1/sqrt(64)
    }

    // ---- softmax across the warp's 128 scores ----
    float m = fmaxf(fmaxf(s[0], s[1]), fmaxf(s[2], s[3]));
    #pragma unroll
    for (int off = 16; off; off >>= 1)
        m = fmaxf(m, __shfl_xor_sync(0xffffffffu, m, off));
    float e[4], sum = 0.f;
    #pragma unroll
    for (int t = 0; t < 4; t++) { e[t] = __expf(s[t] - m); sum += e[t]; }
    #pragma unroll
    for (int off = 16; off; off >>= 1)
        sum += __shfl_xor_sync(0xffffffffu, sum, off);
    const float inv = 1.0f / sum;
    #pragma unroll
    for (int t = 0; t < 4; t++) spb[h][lane + t * 32] = e[t];
    __syncwarp();

    // ---- Phase B: output (lane owns dims 2*lane, 2*lane+1; coalesced) ----
    float o0 = 0.f, o1 = 0.f;
    const int d0 = 2 * lane;
    #pragma unroll 8
    for (int f = 0; f < 128; f++) {
        const float2 k2 = *(const float2*)(g_q + (size_t)spos[f] * DDIM + h * 64 + d0);
        const float pf = spb[h][f];
        o0 = fmaf(pf, k2.x, o0);
        o1 = fmaf(pf, k2.y, o1);
    }
    float2 ov;
    ov.x = o0 * inv;
    ov.y = o1 * inv;
    *(float2*)(g_ao + (size_t)bq * DDIM + h * 64 + d0) = ov;
}

// ---------------------------------------------------------------------------
extern "C" void kernel_launch(void* const* d_in, const int* in_sizes, int n_in,
                              void* d_out, int out_size)
{
    const float* x  = (const float*)d_in[0];
    const float* Wq = (const float*)d_in[1];
    const float* Wo = (const float*)d_in[2];
    const float* bo = (const float*)d_in[3];
    float* out = (float*)d_out;

    float *qp = nullptr, *aop = nullptr;
    cudaGetSymbolAddress((void**)&qp,  g_q);
    cudaGetSymbolAddress((void**)&aop, g_ao);

    const dim3 gridG(512 / BN, ROWS / BM);   // (8, 24)

    // 1) q = x @ Wq^T
    gemm_nt<<<gridG, 256>>>(x, Wq, nullptr, qp, ROWS, 512, 512);
    // 2) gathered attention
    attn_kernel<<<ROWS, 256>>>();
    // 3) out = ao @ Wo^T + bo
    gemm_nt<<<gridG, 256>>>(aop, Wo, bo, out, ROWS, 512, 512);
}

// round 2
// speedup vs baseline: 2.1206x; 2.1206x over previous
#include <cuda_runtime.h>
#include <cstddef>

#define DDIM 512
#define ROWS 3072

__device__ float g_q [ROWS * DDIM];
__device__ float g_ao[ROWS * DDIM];
__device__ float g_S [ROWS * 8 * 128];   // scores, then normalized probs (in place)

// ---------------------------------------------------------------------------
// GEMM: C[M,N] = A[M,K] @ B[N,K]^T (+bias). BM=128,BN=64,BK=16, 128 thr, 8x8.
// ---------------------------------------------------------------------------
#define BM 128
#define BN 64
#define BK 16

__global__ __launch_bounds__(128) void gemm_nt(
    const float* __restrict__ A, const float* __restrict__ B,
    const float* __restrict__ bias, float* __restrict__ C,
    int M, int N, int K)
{
    __shared__ float As[BK][BM + 4];
    __shared__ float Bs[BK][BN + 4];
    const int bm = blockIdx.y * BM;
    const int bn = blockIdx.x * BN;
    const int tid = threadIdx.x;
    const int tx = tid & 7;     // 8 col-tiles of 8
    const int ty = tid >> 3;    // 16 row-tiles of 8

    float acc[8][8];
    #pragma unroll
    for (int u = 0; u < 8; u++)
        #pragma unroll
        for (int v = 0; v < 8; v++) acc[u][v] = 0.f;

    for (int k0 = 0; k0 < K; k0 += BK) {
        #pragma unroll
        for (int it = 0; it < 4; it++) {
            int c = tid + 128 * it;
            int row = c >> 2, kc = (c & 3) * 4;
            float4 v = *(const float4*)(A + (size_t)(bm + row) * K + k0 + kc);
            As[kc + 0][row] = v.x; As[kc + 1][row] = v.y;
            As[kc + 2][row] = v.z; As[kc + 3][row] = v.w;
        }
        #pragma unroll
        for (int it = 0; it < 2; it++) {
            int c = tid + 128 * it;
            int row = c >> 2, kc = (c & 3) * 4;
            float4 v = *(const float4*)(B + (size_t)(bn + row) * K + k0 + kc);
            Bs[kc + 0][row] = v.x; Bs[kc + 1][row] = v.y;
            Bs[kc + 2][row] = v.z; Bs[kc + 3][row] = v.w;
        }
        __syncthreads();
        #pragma unroll
        for (int kk = 0; kk < BK; kk++) {
            float a[8], b[8];
            *(float4*)&a[0] = *(const float4*)&As[kk][ty * 8];
            *(float4*)&a[4] = *(const float4*)&As[kk][ty * 8 + 4];
            *(float4*)&b[0] = *(const float4*)&Bs[kk][tx * 8];
            *(float4*)&b[4] = *(const float4*)&Bs[kk][tx * 8 + 4];
            #pragma unroll
            for (int u = 0; u < 8; u++)
                #pragma unroll
                for (int v = 0; v < 8; v++)
                    acc[u][v] = fmaf(a[u], b[v], acc[u][v]);
        }
        __syncthreads();
    }

    float bv[8] = {0,0,0,0,0,0,0,0};
    if (bias) {
        *(float4*)&bv[0] = *(const float4*)(bias + bn + tx * 8);
        *(float4*)&bv[4] = *(const float4*)(bias + bn + tx * 8 + 4);
    }
    #pragma unroll
    for (int u = 0; u < 8; u++) {
        float* crow = C + (size_t)(bm + ty * 8 + u) * N + bn + tx * 8;
        *(float4*)(crow)     = make_float4(acc[u][0]+bv[0], acc[u][1]+bv[1],
                                           acc[u][2]+bv[2], acc[u][3]+bv[3]);
        *(float4*)(crow + 4) = make_float4(acc[u][4]+bv[4], acc[u][5]+bv[5],
                                           acc[u][6]+bv[6], acc[u][7]+bv[7]);
    }
}

// ---------------------------------------------------------------------------
// Key index mapping (verified in round 1).
// Per plane: one group depends only on i, one only on j, two are fixed.
//   j-dep group id = 3 - p   (p0:g3, p1:g2, p2:g1); the other 3 are i/fixed.
// ---------------------------------------------------------------------------
__device__ __forceinline__ int key_gpos(int p, int f, int i, int j)
{
    const int g = f >> 5;
    const int r = f & 31;
    int pos, sp;
    if (p == 0) {
        sp = (f < 64) ? 1 : 2;
        pos = (g == 0) ? r * 32 + i
            : (g == 1) ? 480 + r
            : (g == 2) ? r * 32 + 15
            :            j * 32 + r;
    } else if (p == 1) {
        sp = (f < 64) ? 0 : 2;
        pos = (g == 0) ? r * 32 + i
            : (g == 1) ? 480 + r
            : (g == 2) ? r * 32 + (31 - j)
            :            480 + r;
    } else {
        sp = (f < 64) ? 0 : 2;
        pos = (g == 0) ? r * 32 + 15
            : (g == 1) ? j * 32 + r
            : (g == 2) ? r * 32 + 15
            :            (31 - i) * 32 + r;
    }
    return sp * 1024 + pos;
}

// slot s in [0,96) -> f index, skipping the j-dependent group (3-p)
__device__ __forceinline__ int k1_f(int p, int s)
{
    int g = s >> 5;
    if (g >= 3 - p) g++;
    return g * 32 + (s & 31);
}

// ---------------------------------------------------------------------------
// K1: scores for 96 i-dep/fixed keys. CTA = (i, head-pair, p); 32 queries (j).
// S[32q,96f] = Q[32,64] @ K[96,64]^T, keys staged once in smem per head.
// ---------------------------------------------------------------------------
__global__ __launch_bounds__(256) void k1_scores()
{
    const int i   = blockIdx.x;
    const int hp  = blockIdx.y;
    const int p   = blockIdx.z;
    const int tid = threadIdx.x;

    __shared__ int   spos[96];
    __shared__ float Ks[64][97];   // [d][s]
    __shared__ float Qs[64][34];   // [d][q] (even pitch for float2)

    if (tid < 96) spos[tid] = key_gpos(p, k1_f(p, tid), i, 0);

    const int qy = tid >> 4;   // 0..15 -> q pair
    const int fx = tid & 15;   // 0..15 -> 6 f each (stride 16)

    for (int e = 0; e < 2; e++) {
        const int h = hp * 2 + e;
        __syncthreads();
        #pragma unroll
        for (int it = 0; it < 2; it++) {
            int c = tid + 256 * it;
            int row = c >> 4, d4 = (c & 15) * 4;
            float4 v = *(const float4*)(g_q + (size_t)(p*1024 + row*32 + i) * DDIM + h*64 + d4);
            Qs[d4+0][row]=v.x; Qs[d4+1][row]=v.y; Qs[d4+2][row]=v.z; Qs[d4+3][row]=v.w;
        }
        #pragma unroll
        for (int it = 0; it < 6; it++) {
            int c = tid + 256 * it;
            int key = c >> 4, d4 = (c & 15) * 4;
            float4 v = *(const float4*)(g_q + (size_t)spos[key] * DDIM + h*64 + d4);
            Ks[d4+0][key]=v.x; Ks[d4+1][key]=v.y; Ks[d4+2][key]=v.z; Ks[d4+3][key]=v.w;
        }
        __syncthreads();

        float acc0[6], acc1[6];
        #pragma unroll
        for (int t = 0; t < 6; t++) { acc0[t] = 0.f; acc1[t] = 0.f; }
        #pragma unroll 16
        for (int d = 0; d < 64; d++) {
            float2 q2 = *(const float2*)&Qs[d][qy * 2];
            #pragma unroll
            for (int t = 0; t < 6; t++) {
                float kv = Ks[d][fx + 16 * t];
                acc0[t] = fmaf(q2.x, kv, acc0[t]);
                acc1[t] = fmaf(q2.y, kv, acc1[t]);
            }
        }
        #pragma unroll
        for (int ee = 0; ee < 2; ee++) {
            const int q = qy * 2 + ee;
            size_t base = ((size_t)(p*1024 + q*32 + i) * 8 + h) * 128;
            const float* ap = ee ? acc1 : acc0;
            #pragma unroll
            for (int t = 0; t < 6; t++)
                g_S[base + k1_f(p, fx + 16 * t)] = ap[t] * 0.125f;
        }
    }
}

// ---------------------------------------------------------------------------
// K2: j-dep scores + softmax over 128 + j-part of output. CTA = (j, hp, p);
// queries contiguous. Writes normalized P to g_S (in place) and O_j to g_ao.
// ---------------------------------------------------------------------------
__global__ __launch_bounds__(256) void k2_mid()
{
    const int j   = blockIdx.x;
    const int hp  = blockIdx.y;
    const int p   = blockIdx.z;
    const int tid = threadIdx.x;
    const int k2g = 3 - p;
    const int qbase = p * 1024 + j * 32;

    __shared__ int   spos[32];
    __shared__ float Kd[64][33];    // [d][f] for scores
    __shared__ float Kf[32][68];    // [f][d] for output
    __shared__ float Qs[64][34];    // [d][q]
    __shared__ float Sall[32][132]; // [q][128 scores/probs]

    if (tid < 32) spos[tid] = key_gpos(p, k2g * 32 + tid, 0, j);

    const int qy = tid >> 4, fx = tid & 15;
    const int qs = tid >> 3, l8 = tid & 7;

    for (int e = 0; e < 2; e++) {
        const int h = hp * 2 + e;
        __syncthreads();
        #pragma unroll
        for (int it = 0; it < 2; it++) {
            int c = tid + 256 * it;
            int row = c >> 4, d4 = (c & 15) * 4;
            float4 v = *(const float4*)(g_q + (size_t)(qbase + row) * DDIM + h*64 + d4);
            Qs[d4+0][row]=v.x; Qs[d4+1][row]=v.y; Qs[d4+2][row]=v.z; Qs[d4+3][row]=v.w;
        }
        #pragma unroll
        for (int it = 0; it < 2; it++) {
            int c = tid + 256 * it;
            int key = c >> 4, d4 = (c & 15) * 4;
            float4 v = *(const float4*)(g_q + (size_t)spos[key] * DDIM + h*64 + d4);
            Kd[d4+0][key]=v.x; Kd[d4+1][key]=v.y; Kd[d4+2][key]=v.z; Kd[d4+3][key]=v.w;
            *(float4*)&Kf[key][d4] = v;
        }
        #pragma unroll
        for (int it = 0; it < 4; it++) {
            int c = tid + 256 * it;
            int q = c >> 5, f4 = (c & 31) * 4;
            *(float4*)&Sall[q][f4] =
                *(const float4*)(g_S + ((size_t)(qbase + q) * 8 + h) * 128 + f4);
        }
        __syncthreads();

        // scores for the 32 j-dep keys
        float a00 = 0.f, a01 = 0.f, a10 = 0.f, a11 = 0.f;
        #pragma unroll 16
        for (int d = 0; d < 64; d++) {
            float2 q2 = *(const float2*)&Qs[d][qy * 2];
            float k0 = Kd[d][fx], k1 = Kd[d][fx + 16];
            a00 = fmaf(q2.x, k0, a00); a01 = fmaf(q2.x, k1, a01);
            a10 = fmaf(q2.y, k0, a10); a11 = fmaf(q2.y, k1, a11);
        }
        Sall[qy*2  ][k2g*32 + fx]      = a00 * 0.125f;
        Sall[qy*2  ][k2g*32 + fx + 16] = a01 * 0.125f;
        Sall[qy*2+1][k2g*32 + fx]      = a10 * 0.125f;
        Sall[qy*2+1][k2g*32 + fx + 16] = a11 * 0.125f;
        __syncthreads();

        // softmax over 128 (8 lanes per query, 16 vals each)
        float vals[16];
        float m = -1e30f;
        #pragma unroll
        for (int u = 0; u < 16; u++) {
            vals[u] = Sall[qs][l8 + 8 * u];
            m = fmaxf(m, vals[u]);
        }
        #pragma unroll
        for (int off = 4; off; off >>= 1)
            m = fmaxf(m, __shfl_xor_sync(0xffffffffu, m, off));
        float sum = 0.f;
        #pragma unroll
        for (int u = 0; u < 16; u++) { vals[u] = __expf(vals[u] - m); sum += vals[u]; }
        #pragma unroll
        for (int off = 4; off; off >>= 1)
            sum += __shfl_xor_sync(0xffffffffu, sum, off);
        const float inv = 1.0f / sum;
        size_t pbase = ((size_t)(qbase + qs) * 8 + h) * 128;
        #pragma unroll
        for (int u = 0; u < 16; u++) {
            float pv = vals[u] * inv;
            int f = l8 + 8 * u;
            Sall[qs][f] = pv;
            g_S[pbase + f] = pv;
        }
        __syncthreads();

        // O_j = P_j(32x32) @ K_j(32x64)
        float4 o0 = make_float4(0,0,0,0), o1 = make_float4(0,0,0,0);
        #pragma unroll 8
        for (int r = 0; r < 32; r++) {
            float pa = Sall[qy*2  ][k2g*32 + r];
            float pb = Sall[qy*2+1][k2g*32 + r];
            float4 kv = *(const float4*)&Kf[r][4 * fx];
            o0.x = fmaf(pa, kv.x, o0.x); o0.y = fmaf(pa, kv.y, o0.y);
            o0.z = fmaf(pa, kv.z, o0.z); o0.w = fmaf(pa, kv.w, o0.w);
            o1.x = fmaf(pb, kv.x, o1.x); o1.y = fmaf(pb, kv.y, o1.y);
            o1.z = fmaf(pb, kv.z, o1.z); o1.w = fmaf(pb, kv.w, o1.w);
        }
        *(float4*)(g_ao + (size_t)(qbase + qy*2    ) * DDIM + h*64 + 4*fx) = o0;
        *(float4*)(g_ao + (size_t)(qbase + qy*2 + 1) * DDIM + h*64 + 4*fx) = o1;
    }
}

// ---------------------------------------------------------------------------
// K3: i-part of output. CTA = (i, hp, p). O += P_96(32x96) @ K_96(96x64).
// ---------------------------------------------------------------------------
__global__ __launch_bounds__(256) void k3_out()
{
    const int i   = blockIdx.x;
    const int hp  = blockIdx.y;
    const int p   = blockIdx.z;
    const int tid = threadIdx.x;

    __shared__ int   spos[96];
    __shared__ float Ks[96][68];   // [s][d]
    __shared__ float Ps[32][100];  // [q][s]

    if (tid < 96) spos[tid] = key_gpos(p, k1_f(p, tid), i, 0);

    const int qy = tid >> 4, dx = tid & 15;
    const int qs = tid >> 3, l8 = tid & 7;

    for (int e = 0; e < 2; e++) {
        const int h = hp * 2 + e;
        __syncthreads();
        #pragma unroll
        for (int it = 0; it < 6; it++) {
            int c = tid + 256 * it;
            int key = c >> 4, d4 = (c & 15) * 4;
            *(float4*)&Ks[key][d4] =
                *(const float4*)(g_q + (size_t)spos[key] * DDIM + h*64 + d4);
        }
        #pragma unroll
        for (int v = 0; v < 3; v++) {
            int s0 = 4 * (l8 + 8 * v);
            int f0 = k1_f(p, s0);
            *(float4*)&Ps[qs][s0] =
                *(const float4*)(g_S + ((size_t)(p*1024 + qs*32 + i) * 8 + h) * 128 + f0);
        }
        __syncthreads();

        float4 o0 = make_float4(0,0,0,0), o1 = make_float4(0,0,0,0);
        #pragma unroll 8
        for (int s = 0; s < 96; s++) {
            float pa = Ps[qy*2  ][s];
            float pb = Ps[qy*2+1][s];
            float4 kv = *(const float4*)&Ks[s][4 * dx];
            o0.x = fmaf(pa, kv.x, o0.x); o0.y = fmaf(pa, kv.y, o0.y);
            o0.z = fmaf(pa, kv.z, o0.z); o0.w = fmaf(pa, kv.w, o0.w);
            o1.x = fmaf(pb, kv.x, o1.x); o1.y = fmaf(pb, kv.y, o1.y);
            o1.z = fmaf(pb, kv.z, o1.z); o1.w = fmaf(pb, kv.w, o1.w);
        }
        size_t off0 = (size_t)(p*1024 + (qy*2    )*32 + i) * DDIM + h*64 + 4*dx;
        size_t off1 = (size_t)(p*1024 + (qy*2 + 1)*32 + i) * DDIM + h*64 + 4*dx;
        float4 v0 = *(const float4*)(g_ao + off0);
        float4 v1 = *(const float4*)(g_ao + off1);
        o0.x += v0.x; o0.y += v0.y; o0.z += v0.z; o0.w += v0.w;
        o1.x += v1.x; o1.y += v1.y; o1.z += v1.z; o1.w += v1.w;
        *(float4*)(g_ao + off0) = o0;
        *(float4*)(g_ao + off1) = o1;
    }
}

// ---------------------------------------------------------------------------
extern "C" void kernel_launch(void* const* d_in, const int* in_sizes, int n_in,
                              void* d_out, int out_size)
{
    const float* x  = (const float*)d_in[0];
    const float* Wq = (const float*)d_in[1];
    const float* Wo = (const float*)d_in[2];
    const float* bo = (const float*)d_in[3];
    float* out = (float*)d_out;

    float *qp = nullptr, *aop = nullptr;
    cudaGetSymbolAddress((void**)&qp,  g_q);
    cudaGetSymbolAddress((void**)&aop, g_ao);

    const dim3 gridG(512 / BN, ROWS / BM);   // (8, 24)
    const dim3 gridA(32, 4, 3);              // (i|j, head-pair, plane)

    gemm_nt<<<gridG, 128>>>(x, Wq, nullptr, qp, ROWS, 512, 512);
    k1_scores<<<gridA, 256>>>();
    k2_mid  <<<gridA, 256>>>();
    k3_out  <<<gridA, 256>>>();
    gemm_nt<<<gridG, 128>>>(aop, Wo, bo, out, ROWS, 512, 512);
}